// round 8
// baseline (speedup 1.0000x reference)
#include <cuda_runtime.h>
#include <cuda_bf16.h>
#include <math_constants.h>

// Problem dims
#define Bn   8
#define An   64
#define Ln   30
#define Dn   128
#define Kn   16
#define Mn   128
#define Hn   8
#define HDn  16
#define NROWS (Bn*An*Ln)           // 15360
#define JTOT (Kn*Ln)               // 480
#define SCP  481                   // padded score stride
#define SCALE 0.25f

// ---- packed f32x2 helpers (Blackwell FFMA2 path) ---------------------------
typedef unsigned long long u64;
union F4U2 { float4 f; u64 u[2]; };

__device__ __forceinline__ u64 pack2(float lo, float hi) {
    u64 r; asm("mov.b64 %0, {%1,%2};" : "=l"(r) : "f"(lo), "f"(hi)); return r;
}
__device__ __forceinline__ void unpack2(u64 v, float& lo, float& hi) {
    asm("mov.b64 {%0,%1}, %2;" : "=f"(lo), "=f"(hi) : "l"(v));
}
__device__ __forceinline__ u64 fma2(u64 a, u64 b, u64 c) {
    u64 d; asm("fma.rn.f32x2 %0, %1, %2, %3;" : "=l"(d) : "l"(a), "l"(b), "l"(c)); return d;
}

// Scratch (device globals; no allocation allowed)
__device__ float g_q[NROWS*Mn];
__device__ float g_k[NROWS*Mn];
__device__ float g_v[NROWS*Mn];
__device__ float g_ctx[NROWS*Mn];
__device__ int   g_mask_mode;      // 0 = u8/bool, 1 = int32, 2 = float32

// ---------------------------------------------------------------------------
__global__ void __launch_bounds__(256) detect_mask_kernel(const unsigned int* __restrict__ m)
{
    __shared__ int s_f32, s_hi;
    if (threadIdx.x == 0) { s_f32 = 0; s_hi = 0; }
    __syncthreads();
    int f32 = 0, hi = 0;
#pragma unroll
    for (int i = 0; i < 8; i++) {
        unsigned int w = m[threadIdx.x + 256*i];
        f32 |= (w == 0x3f800000u);
        hi  |= ((w & 0xFFFFFF00u) != 0u);
    }
    if (f32) s_f32 = 1;
    if (hi)  s_hi  = 1;
    __syncthreads();
    if (threadIdx.x == 0)
        g_mask_mode = s_f32 ? 2 : (s_hi ? 0 : 1);
}

// ---------------------------------------------------------------------------
// GEMM core: 64x128 CTA tile, thread owns 4 rows x 8 consecutive cols.
// ---------------------------------------------------------------------------
__device__ __forceinline__ void gemm_body(
    const float* __restrict__ X, const float* __restrict__ W,
    const float* __restrict__ bias, float* __restrict__ C,
    float* sm, int row0, int tid)
{
    float* Xs = sm;                 // 64 x 129
    float* Ws = sm + 64*129;        // 128 x 128

    const float4* Xg = reinterpret_cast<const float4*>(X + (size_t)row0 * 128);
    const float4* Wg = reinterpret_cast<const float4*>(W);
    float4* Ws4 = reinterpret_cast<float4*>(Ws);
#pragma unroll
    for (int i = 0; i < 8; i++) {
        int idx = tid + 256*i;
        float4 v = Xg[idx];
        int r = idx >> 5;
        int c = (idx & 31) * 4;
        Xs[r*129 + c + 0] = v.x;
        Xs[r*129 + c + 1] = v.y;
        Xs[r*129 + c + 2] = v.z;
        Xs[r*129 + c + 3] = v.w;
    }
#pragma unroll
    for (int i = 0; i < 16; i++) Ws4[tid + 256*i] = Wg[tid + 256*i];
    __syncthreads();

    const int tx = tid & 15;
    const int ty = tid >> 4;
    u64 acc[4][4];
#pragma unroll
    for (int i = 0; i < 4; i++)
#pragma unroll
        for (int j = 0; j < 4; j++) acc[i][j] = 0ULL;

#pragma unroll 8
    for (int k = 0; k < 128; k++) {
        u64 aa[4];
#pragma unroll
        for (int i = 0; i < 4; i++) {
            float a = Xs[(ty + 16*i)*129 + k];
            aa[i] = pack2(a, a);
        }
        F4U2 b0, b1;
        b0.f = Ws4[k*32 + tx*2 + 0];
        b1.f = Ws4[k*32 + tx*2 + 1];
        u64 bb[4] = {b0.u[0], b0.u[1], b1.u[0], b1.u[1]};
#pragma unroll
        for (int i = 0; i < 4; i++)
#pragma unroll
            for (int j = 0; j < 4; j++) acc[i][j] = fma2(aa[i], bb[j], acc[i][j]);
    }

    const float4* bias4 = reinterpret_cast<const float4*>(bias);
    float4 bb0 = bias4[tx*2 + 0];
    float4 bb1 = bias4[tx*2 + 1];
    float bb[8] = {bb0.x, bb0.y, bb0.z, bb0.w, bb1.x, bb1.y, bb1.z, bb1.w};
#pragma unroll
    for (int i = 0; i < 4; i++) {
        int r = row0 + ty + 16*i;
        float av[8];
#pragma unroll
        for (int j = 0; j < 4; j++) unpack2(acc[i][j], av[j*2], av[j*2+1]);
        float4* dst = reinterpret_cast<float4*>(C + (size_t)r*128 + tx*8);
        dst[0] = make_float4(av[0]+bb[0], av[1]+bb[1], av[2]+bb[2], av[3]+bb[3]);
        dst[1] = make_float4(av[4]+bb[4], av[5]+bb[5], av[6]+bb[6], av[7]+bb[7]);
    }
}

__global__ void __launch_bounds__(256, 2) gemm_qkv_kernel(
    const float* __restrict__ X,
    const float* __restrict__ Wq, const float* __restrict__ bq, float* __restrict__ Cq,
    const float* __restrict__ Wk, const float* __restrict__ bk, float* __restrict__ Ck,
    const float* __restrict__ Wv, const float* __restrict__ bv, float* __restrict__ Cv)
{
    const float* W; const float* bias; float* C;
    if (blockIdx.y == 0)      { W = Wq; bias = bq; C = Cq; }
    else if (blockIdx.y == 1) { W = Wk; bias = bk; C = Ck; }
    else                      { W = Wv; bias = bv; C = Cv; }
    extern __shared__ float sm[];
    gemm_body(X, W, bias, C, sm, blockIdx.x * 64, threadIdx.x);
}

__global__ void __launch_bounds__(256, 2) gemm64_kernel(
    const float* __restrict__ X, const float* __restrict__ W,
    const float* __restrict__ bias, float* __restrict__ C)
{
    extern __shared__ float sm[];
    gemm_body(X, W, bias, C, sm, blockIdx.x * 64, threadIdx.x);
}

// ---------------------------------------------------------------------------
// Attention: one 256-thread CTA per (b, a, h); 3 CTAs/SM (24 warps).
// smem: qs[30*16] | sc[30*481]  = 59640 B.  K and V come straight from global.
// ---------------------------------------------------------------------------
__global__ void __launch_bounds__(256, 3) attn_kernel(
    const float* __restrict__ gq, const float* __restrict__ gk,
    const float* __restrict__ gv, const float* __restrict__ geom_bias,
    const int* __restrict__ nidx, const void* __restrict__ nmask,
    float* __restrict__ attn_out, float* __restrict__ ctx_out, int blk_off)
{
    const int bid = blockIdx.x + blk_off;
    const int h  = bid & 7;
    const int a  = (bid >> 3) & 63;
    const int b  = bid >> 9;
    const int ba = b*An + a;
    const int tid = threadIdx.x;

    extern __shared__ float sm[];
    float* qs = sm;                    // 480 floats
    float* sc = qs + Ln*HDn;           // 30*481 (scores / later partials)

    __shared__ int   rowbase[Kn];
    __shared__ float biasS[Kn];
    __shared__ int   maskS[Kn];

    if (tid < Kn) {
        int n = nidx[ba*Kn + tid];
        rowbase[tid] = (b*An + n) * Ln * Dn;
        biasS[tid]   = geom_bias[ba*Kn + tid];
        int mode = g_mask_mode;
        bool mv;
        if (mode == 0)      mv = ((const unsigned char*)nmask)[ba*Kn + tid] != 0;
        else if (mode == 1) mv = ((const int*)nmask)[ba*Kn + tid] != 0;
        else                mv = ((const float*)nmask)[ba*Kn + tid] != 0.0f;
        maskS[tid] = mv ? 1 : 0;
    }
    // q head slice: 120 float4
    {
        const float* qbase = gq + (size_t)ba*Ln*Mn + h*HDn;
        for (int i = tid; i < Ln*4; i += 256) {
            int r = i >> 2, c = (i & 3) * 4;
            float4 v = *reinterpret_cast<const float4*>(qbase + r*Mn + c);
            qs[r*HDn + c + 0] = v.x; qs[r*HDn + c + 1] = v.y;
            qs[r*HDn + c + 2] = v.z; qs[r*HDn + c + 3] = v.w;
        }
    }
    __syncthreads();   // rowbase/bias/mask + qs ready

    // K rows straight from global into PACKED registers: thread owns j0, j1
    const int j0 = tid;
    const int j1 = tid + 256;
    const bool hasJ1 = (tid < JTOT - 256);   // tid < 224
    const int kk0 = j0 / Ln;
    const int l0  = j0 - kk0*Ln;
    const int kk1 = j1 / Ln;
    const int l1  = j1 - kk1*Ln;
    u64 k0[8], k1[8];
    {
        const float4* src0 = reinterpret_cast<const float4*>(gk + rowbase[kk0] + l0*Mn + h*HDn);
        F4U2 t;
#pragma unroll
        for (int c = 0; c < 4; c++) {
            t.f = src0[c];
            k0[c*2+0] = t.u[0]; k0[c*2+1] = t.u[1];
        }
        if (hasJ1) {
            const float4* src1 = reinterpret_cast<const float4*>(gk + rowbase[kk1] + l1*Mn + h*HDn);
#pragma unroll
            for (int c = 0; c < 4; c++) {
                t.f = src1[c];
                k1[c*2+0] = t.u[0]; k1[c*2+1] = t.u[1];
            }
        }
    }
    const float bias0 = biasS[kk0];
    const bool  m0 = maskS[kk0] != 0;
    const float bias1 = hasJ1 ? biasS[kk1] : 0.f;
    const bool  m1 = hasJ1 ? (maskS[kk1] != 0) : false;

    // scores from packed register K
    const float NEGINF = -CUDART_INF_F;
    const float4* qs4 = reinterpret_cast<const float4*>(qs);
#pragma unroll 1
    for (int qp = 0; qp < Ln/2; qp++) {
        int q0 = qp * 2;
        u64 qa[8], qb[8];
        {
            F4U2 t;
#pragma unroll
            for (int c = 0; c < 4; c++) {
                t.f = qs4[q0*4 + c];
                qa[c*2+0] = t.u[0]; qa[c*2+1] = t.u[1];
            }
#pragma unroll
            for (int c = 0; c < 4; c++) {
                t.f = qs4[(q0+1)*4 + c];
                qb[c*2+0] = t.u[0]; qb[c*2+1] = t.u[1];
            }
        }
        u64 p00 = 0ULL, p10 = 0ULL, p01 = 0ULL, p11 = 0ULL;
#pragma unroll
        for (int d = 0; d < 8; d++) {
            p00 = fma2(qa[d], k0[d], p00);
            p10 = fma2(qb[d], k0[d], p10);
        }
        if (hasJ1) {
#pragma unroll
            for (int d = 0; d < 8; d++) {
                p01 = fma2(qa[d], k1[d], p01);
                p11 = fma2(qb[d], k1[d], p11);
            }
        }
        float lo, hi;
        unpack2(p00, lo, hi); float s00 = lo + hi;
        unpack2(p10, lo, hi); float s10 = lo + hi;
        sc[q0*SCP + j0]     = m0 ? fmaf(s00, SCALE, bias0) : NEGINF;
        sc[(q0+1)*SCP + j0] = m0 ? fmaf(s10, SCALE, bias0) : NEGINF;
        if (hasJ1) {
            unpack2(p01, lo, hi); float s01 = lo + hi;
            unpack2(p11, lo, hi); float s11 = lo + hi;
            sc[q0*SCP + j1]     = m1 ? fmaf(s01, SCALE, bias1) : NEGINF;
            sc[(q0+1)*SCP + j1] = m1 ? fmaf(s11, SCALE, bias1) : NEGINF;
        }
    }
    __syncthreads();

    // softmax: one warp per row, 15 elements per lane held in registers
    {
        const int warp = tid >> 5, lane = tid & 31;
        for (int q = warp; q < Ln; q += 8) {
            float* row = sc + q*SCP;
            float* arow = attn_out + ((size_t)(ba*Hn + h)*Ln + q) * JTOT;
            float p[15];
#pragma unroll
            for (int i = 0; i < 15; i++) p[i] = row[i*32 + lane];
            float m = p[0];
#pragma unroll
            for (int i = 1; i < 15; i++) m = fmaxf(m, p[i]);
#pragma unroll
            for (int off = 16; off; off >>= 1) m = fmaxf(m, __shfl_xor_sync(0xffffffffu, m, off));
            if (m == NEGINF) {
#pragma unroll
                for (int i = 0; i < 15; i++) { row[i*32 + lane] = 0.f; arow[i*32 + lane] = 0.f; }
            } else {
                float s = 0.f;
#pragma unroll
                for (int i = 0; i < 15; i++) { p[i] = __expf(p[i] - m); s += p[i]; }
#pragma unroll
                for (int off = 16; off; off >>= 1) s += __shfl_xor_sync(0xffffffffu, s, off);
                float inv = 1.f / s;
#pragma unroll
                for (int i = 0; i < 15; i++) {
                    float v = p[i] * inv;
                    row[i*32 + lane] = v;
                    arow[i*32 + lane] = v;
                }
            }
        }
    }
    __syncthreads();

    // P @ V : warp w owns j in [60w, 60w+60) = kk 2w, 2w+1; lane = q row.
    // V read directly from global (broadcast LDG per line, L2-resident).
    const int w    = tid >> 5;
    const int lane = tid & 31;
    u64 acc[8];
#pragma unroll
    for (int d = 0; d < 8; d++) acc[d] = 0ULL;
    if (lane < Ln) {
        const float* prow = sc + lane*SCP;
#pragma unroll
        for (int half = 0; half < 2; half++) {
            const int kk = 2*w + half;
            const float4* vbase = reinterpret_cast<const float4*>(gv + rowbase[kk] + h*HDn);
            const int jbase = kk*Ln;
#pragma unroll 3
            for (int l = 0; l < Ln; l++) {
                float p = prow[jbase + l];
                u64 pp = pack2(p, p);
                const float4* src = vbase + l*(Mn/4);
                F4U2 v0, v1, v2, v3;
                v0.f = src[0]; v1.f = src[1]; v2.f = src[2]; v3.f = src[3];
                acc[0] = fma2(pp, v0.u[0], acc[0]); acc[1] = fma2(pp, v0.u[1], acc[1]);
                acc[2] = fma2(pp, v1.u[0], acc[2]); acc[3] = fma2(pp, v1.u[1], acc[3]);
                acc[4] = fma2(pp, v2.u[0], acc[4]); acc[5] = fma2(pp, v2.u[1], acc[5]);
                acc[6] = fma2(pp, v3.u[0], acc[6]); acc[7] = fma2(pp, v3.u[1], acc[7]);
            }
        }
    }
    __syncthreads();   // sc reads done; region reusable for partials
    if (lane < Ln) {
        float av[16];
#pragma unroll
        for (int d = 0; d < 8; d++) unpack2(acc[d], av[2*d], av[2*d+1]);
        float4* dst = reinterpret_cast<float4*>(sc + w*480 + lane*HDn);
#pragma unroll
        for (int c = 0; c < 4; c++)
            dst[c] = make_float4(av[c*4+0], av[c*4+1], av[c*4+2], av[c*4+3]);
    }
    __syncthreads();

    // reduce 8 partials and write ctx slice
    for (int e = tid; e < Ln*HDn; e += 256) {
        float s = 0.f;
#pragma unroll
        for (int ww = 0; ww < 8; ww++) s += sc[ww*480 + e];
        int q = e >> 4, d = e & 15;
        ctx_out[((size_t)ba*Ln + q)*Mn + h*HDn + d] = s;
    }
}

// ---------------------------------------------------------------------------
extern "C" void kernel_launch(void* const* d_in, const int* in_sizes, int n_in,
                              void* d_out, int out_size)
{
    const float* ff   = (const float*)d_in[0];
    const float* gb   = (const float*)d_in[1];
    const float* Wq   = (const float*)d_in[2];
    const float* bq   = (const float*)d_in[3];
    const float* Wk   = (const float*)d_in[4];
    const float* bk   = (const float*)d_in[5];
    const float* Wv   = (const float*)d_in[6];
    const float* bv   = (const float*)d_in[7];
    const float* Wo   = (const float*)d_in[8];
    const float* bo   = (const float*)d_in[9];
    const int*   nidx = (const int*)d_in[10];
    const void*  nmask = (const void*)d_in[11];

    float* out  = (float*)d_out;
    float* attn = out + (size_t)Bn*An*Ln*Mn;

    float *pq, *pk, *pv, *pctx;
    cudaGetSymbolAddress((void**)&pq,  g_q);
    cudaGetSymbolAddress((void**)&pk,  g_k);
    cudaGetSymbolAddress((void**)&pv,  g_v);
    cudaGetSymbolAddress((void**)&pctx, g_ctx);

    const int gemm_smem = (64*129 + 128*128) * 4;          // 98560 B
    const int attn_smem = (Ln*HDn + Ln*SCP) * 4;           // 59640 B
    cudaFuncSetAttribute(gemm_qkv_kernel, cudaFuncAttributeMaxDynamicSharedMemorySize, gemm_smem);
    cudaFuncSetAttribute(gemm64_kernel,   cudaFuncAttributeMaxDynamicSharedMemorySize, gemm_smem);
    cudaFuncSetAttribute(attn_kernel,     cudaFuncAttributeMaxDynamicSharedMemorySize, attn_smem);

    // 1: mask dtype detection
    detect_mask_kernel<<<1, 256>>>((const unsigned int*)nmask);

    // 2: fused QKV projections
    dim3 gqkv(NROWS/64, 3);
    gemm_qkv_kernel<<<gqkv, 256, gemm_smem>>>(ff, Wq, bq, pq, Wk, bk, pk, Wv, bv, pv);

    // 3-6: attention in 4 grid chunks (keeps attn profiled by ncu -s 5 -c 1)
    const int TOTAL = Bn*An*Hn;           // 4096
    const int CH = TOTAL / 4;             // 1024
    attn_kernel<<<CH, 256, attn_smem>>>(pq, pk, pv, gb, nidx, nmask, attn, pctx, 0*CH);
    attn_kernel<<<CH, 256, attn_smem>>>(pq, pk, pv, gb, nidx, nmask, attn, pctx, 1*CH);
    attn_kernel<<<CH, 256, attn_smem>>>(pq, pk, pv, gb, nidx, nmask, attn, pctx, 2*CH);
    attn_kernel<<<CH, 256, attn_smem>>>(pq, pk, pv, gb, nidx, nmask, attn, pctx, 3*CH);

    // 7: output projection
    gemm64_kernel<<<NROWS/64, 256, gemm_smem>>>(pctx, Wo, bo, out);
}

// round 9
// speedup vs baseline: 1.1225x; 1.1225x over previous
#include <cuda_runtime.h>
#include <cuda_bf16.h>
#include <math_constants.h>

// Problem dims
#define Bn   8
#define An   64
#define Ln   30
#define Dn   128
#define Kn   16
#define Mn   128
#define Hn   8
#define HDn  16
#define NROWS (Bn*An*Ln)           // 15360
#define JTOT (Kn*Ln)               // 480
#define SCP  481                   // padded score stride
#define SCALE 0.25f

// ---- packed f32x2 helpers (Blackwell FFMA2 path) ---------------------------
typedef unsigned long long u64;
union F4U2 { float4 f; u64 u[2]; };

__device__ __forceinline__ u64 pack2(float lo, float hi) {
    u64 r; asm("mov.b64 %0, {%1,%2};" : "=l"(r) : "f"(lo), "f"(hi)); return r;
}
__device__ __forceinline__ void unpack2(u64 v, float& lo, float& hi) {
    asm("mov.b64 {%0,%1}, %2;" : "=f"(lo), "=f"(hi) : "l"(v));
}
__device__ __forceinline__ u64 fma2(u64 a, u64 b, u64 c) {
    u64 d; asm("fma.rn.f32x2 %0, %1, %2, %3;" : "=l"(d) : "l"(a), "l"(b), "l"(c)); return d;
}

// Scratch (device globals; no allocation allowed)
__device__ float g_q[NROWS*Mn];
__device__ float g_k[NROWS*Mn];
__device__ float g_v[NROWS*Mn];
__device__ float g_ctx[NROWS*Mn];
__device__ int   g_mask_mode;      // 0 = u8/bool, 1 = int32, 2 = float32

// ---------------------------------------------------------------------------
__global__ void __launch_bounds__(256) detect_mask_kernel(const unsigned int* __restrict__ m)
{
    __shared__ int s_f32, s_hi;
    if (threadIdx.x == 0) { s_f32 = 0; s_hi = 0; }
    __syncthreads();
    int f32 = 0, hi = 0;
#pragma unroll
    for (int i = 0; i < 8; i++) {
        unsigned int w = m[threadIdx.x + 256*i];
        f32 |= (w == 0x3f800000u);
        hi  |= ((w & 0xFFFFFF00u) != 0u);
    }
    if (f32) s_f32 = 1;
    if (hi)  s_hi  = 1;
    __syncthreads();
    if (threadIdx.x == 0)
        g_mask_mode = s_f32 ? 2 : (s_hi ? 0 : 1);
}

// ---------------------------------------------------------------------------
// GEMM core: 64x128 CTA tile, thread owns 4 rows x 8 consecutive cols.
// ---------------------------------------------------------------------------
__device__ __forceinline__ void gemm_body(
    const float* __restrict__ X, const float* __restrict__ W,
    const float* __restrict__ bias, float* __restrict__ C,
    float* sm, int row0, int tid)
{
    float* Xs = sm;                 // 64 x 129
    float* Ws = sm + 64*129;        // 128 x 128

    const float4* Xg = reinterpret_cast<const float4*>(X + (size_t)row0 * 128);
    const float4* Wg = reinterpret_cast<const float4*>(W);
    float4* Ws4 = reinterpret_cast<float4*>(Ws);
#pragma unroll
    for (int i = 0; i < 8; i++) {
        int idx = tid + 256*i;
        float4 v = Xg[idx];
        int r = idx >> 5;
        int c = (idx & 31) * 4;
        Xs[r*129 + c + 0] = v.x;
        Xs[r*129 + c + 1] = v.y;
        Xs[r*129 + c + 2] = v.z;
        Xs[r*129 + c + 3] = v.w;
    }
#pragma unroll
    for (int i = 0; i < 16; i++) Ws4[tid + 256*i] = Wg[tid + 256*i];
    __syncthreads();

    const int tx = tid & 15;
    const int ty = tid >> 4;
    u64 acc[4][4];
#pragma unroll
    for (int i = 0; i < 4; i++)
#pragma unroll
        for (int j = 0; j < 4; j++) acc[i][j] = 0ULL;

#pragma unroll 8
    for (int k = 0; k < 128; k++) {
        u64 aa[4];
#pragma unroll
        for (int i = 0; i < 4; i++) {
            float a = Xs[(ty + 16*i)*129 + k];
            aa[i] = pack2(a, a);
        }
        F4U2 b0, b1;
        b0.f = Ws4[k*32 + tx*2 + 0];
        b1.f = Ws4[k*32 + tx*2 + 1];
        u64 bb[4] = {b0.u[0], b0.u[1], b1.u[0], b1.u[1]};
#pragma unroll
        for (int i = 0; i < 4; i++)
#pragma unroll
            for (int j = 0; j < 4; j++) acc[i][j] = fma2(aa[i], bb[j], acc[i][j]);
    }

    const float4* bias4 = reinterpret_cast<const float4*>(bias);
    float4 bb0 = bias4[tx*2 + 0];
    float4 bb1 = bias4[tx*2 + 1];
    float bb[8] = {bb0.x, bb0.y, bb0.z, bb0.w, bb1.x, bb1.y, bb1.z, bb1.w};
#pragma unroll
    for (int i = 0; i < 4; i++) {
        int r = row0 + ty + 16*i;
        float av[8];
#pragma unroll
        for (int j = 0; j < 4; j++) unpack2(acc[i][j], av[j*2], av[j*2+1]);
        float4* dst = reinterpret_cast<float4*>(C + (size_t)r*128 + tx*8);
        dst[0] = make_float4(av[0]+bb[0], av[1]+bb[1], av[2]+bb[2], av[3]+bb[3]);
        dst[1] = make_float4(av[4]+bb[4], av[5]+bb[5], av[6]+bb[6], av[7]+bb[7]);
    }
}

__global__ void __launch_bounds__(256, 2) gemm_qkv_kernel(
    const float* __restrict__ X,
    const float* __restrict__ Wq, const float* __restrict__ bq, float* __restrict__ Cq,
    const float* __restrict__ Wk, const float* __restrict__ bk, float* __restrict__ Ck,
    const float* __restrict__ Wv, const float* __restrict__ bv, float* __restrict__ Cv)
{
    const float* W; const float* bias; float* C;
    if (blockIdx.y == 0)      { W = Wq; bias = bq; C = Cq; }
    else if (blockIdx.y == 1) { W = Wk; bias = bk; C = Ck; }
    else                      { W = Wv; bias = bv; C = Cv; }
    extern __shared__ float sm[];
    gemm_body(X, W, bias, C, sm, blockIdx.x * 64, threadIdx.x);
}

__global__ void __launch_bounds__(256, 2) gemm64_kernel(
    const float* __restrict__ X, const float* __restrict__ W,
    const float* __restrict__ bias, float* __restrict__ C)
{
    extern __shared__ float sm[];
    gemm_body(X, W, bias, C, sm, blockIdx.x * 64, threadIdx.x);
}

// ---------------------------------------------------------------------------
// Attention: one 256-thread CTA per (b, a, h); 3 CTAs/SM (24 warps).
// smem: qs[30*16] | sc[30*481]  = 59640 B.
// K is STAGED through the sc region (aliased; sc not yet live), then lives in
// registers. V is read directly from global (warp-broadcast, L1-resident).
// ---------------------------------------------------------------------------
__global__ void __launch_bounds__(256, 3) attn_kernel(
    const float* __restrict__ gq, const float* __restrict__ gk,
    const float* __restrict__ gv, const float* __restrict__ geom_bias,
    const int* __restrict__ nidx, const void* __restrict__ nmask,
    float* __restrict__ attn_out, float* __restrict__ ctx_out)
{
    const int bid = blockIdx.x;
    const int h  = bid & 7;
    const int a  = (bid >> 3) & 63;
    const int b  = bid >> 9;
    const int ba = b*An + a;
    const int tid = threadIdx.x;

    extern __shared__ float sm[];
    float* qs = sm;                    // 480 floats
    float* sc = qs + Ln*HDn;           // 30*481 (K staging -> scores -> partials)
    float* kstage = sc;                // alias: 480*17 = 8160 <= 14430 floats

    __shared__ int   rowbase[Kn];
    __shared__ float biasS[Kn];
    __shared__ int   maskS[Kn];

    if (tid < Kn) {
        int n = nidx[ba*Kn + tid];
        rowbase[tid] = (b*An + n) * Ln * Dn;
        biasS[tid]   = geom_bias[ba*Kn + tid];
        int mode = g_mask_mode;
        bool mv;
        if (mode == 0)      mv = ((const unsigned char*)nmask)[ba*Kn + tid] != 0;
        else if (mode == 1) mv = ((const int*)nmask)[ba*Kn + tid] != 0;
        else                mv = ((const float*)nmask)[ba*Kn + tid] != 0.0f;
        maskS[tid] = mv ? 1 : 0;
    }
    // q head slice: 120 float4
    {
        const float* qbase = gq + (size_t)ba*Ln*Mn + h*HDn;
        for (int i = tid; i < Ln*4; i += 256) {
            int r = i >> 2, c = (i & 3) * 4;
            float4 v = *reinterpret_cast<const float4*>(qbase + r*Mn + c);
            qs[r*HDn + c + 0] = v.x; qs[r*HDn + c + 1] = v.y;
            qs[r*HDn + c + 2] = v.z; qs[r*HDn + c + 3] = v.w;
        }
    }
    __syncthreads();   // rowbase ready

    // stage K head slices into (aliased) smem: coalesced gather, stride 17
    for (int i = tid; i < JTOT*4; i += 256) {
        int j = i >> 2, c = (i & 3) * 4;
        int kk = j / Ln, l = j - kk*Ln;
        const float* src = gk + rowbase[kk] + l*Mn + h*HDn + c;
        float4 v = *reinterpret_cast<const float4*>(src);
        kstage[j*17 + c + 0] = v.x; kstage[j*17 + c + 1] = v.y;
        kstage[j*17 + c + 2] = v.z; kstage[j*17 + c + 3] = v.w;
    }
    __syncthreads();

    // K rows into PACKED registers: thread owns j0 = tid, j1 = tid+256
    const int j0 = tid;
    const int j1 = tid + 256;
    const bool hasJ1 = (tid < JTOT - 256);   // tid < 224
    u64 k0[8], k1[8];
#pragma unroll
    for (int d = 0; d < 8; d++) k0[d] = pack2(kstage[j0*17 + 2*d], kstage[j0*17 + 2*d + 1]);
    if (hasJ1) {
#pragma unroll
        for (int d = 0; d < 8; d++) k1[d] = pack2(kstage[j1*17 + 2*d], kstage[j1*17 + 2*d + 1]);
    }
    const int kk0 = j0 / Ln;
    const int kk1 = j1 / Ln;
    const float bias0 = biasS[kk0];
    const bool  m0 = maskS[kk0] != 0;
    const float bias1 = hasJ1 ? biasS[kk1] : 0.f;
    const bool  m1 = hasJ1 ? (maskS[kk1] != 0) : false;
    __syncthreads();   // staging done; sc region free for scores

    // scores from packed register K
    const float NEGINF = -CUDART_INF_F;
    const float4* qs4 = reinterpret_cast<const float4*>(qs);
#pragma unroll 1
    for (int qp = 0; qp < Ln/2; qp++) {
        int q0 = qp * 2;
        u64 qa[8], qb[8];
        {
            F4U2 t;
#pragma unroll
            for (int c = 0; c < 4; c++) {
                t.f = qs4[q0*4 + c];
                qa[c*2+0] = t.u[0]; qa[c*2+1] = t.u[1];
            }
#pragma unroll
            for (int c = 0; c < 4; c++) {
                t.f = qs4[(q0+1)*4 + c];
                qb[c*2+0] = t.u[0]; qb[c*2+1] = t.u[1];
            }
        }
        u64 p00 = 0ULL, p10 = 0ULL, p01 = 0ULL, p11 = 0ULL;
#pragma unroll
        for (int d = 0; d < 8; d++) {
            p00 = fma2(qa[d], k0[d], p00);
            p10 = fma2(qb[d], k0[d], p10);
        }
        if (hasJ1) {
#pragma unroll
            for (int d = 0; d < 8; d++) {
                p01 = fma2(qa[d], k1[d], p01);
                p11 = fma2(qb[d], k1[d], p11);
            }
        }
        float lo, hi;
        unpack2(p00, lo, hi); float s00 = lo + hi;
        unpack2(p10, lo, hi); float s10 = lo + hi;
        sc[q0*SCP + j0]     = m0 ? fmaf(s00, SCALE, bias0) : NEGINF;
        sc[(q0+1)*SCP + j0] = m0 ? fmaf(s10, SCALE, bias0) : NEGINF;
        if (hasJ1) {
            unpack2(p01, lo, hi); float s01 = lo + hi;
            unpack2(p11, lo, hi); float s11 = lo + hi;
            sc[q0*SCP + j1]     = m1 ? fmaf(s01, SCALE, bias1) : NEGINF;
            sc[(q0+1)*SCP + j1] = m1 ? fmaf(s11, SCALE, bias1) : NEGINF;
        }
    }
    __syncthreads();

    // softmax: one warp per row, 15 elements per lane held in registers
    {
        const int warp = tid >> 5, lane = tid & 31;
        for (int q = warp; q < Ln; q += 8) {
            float* row = sc + q*SCP;
            float* arow = attn_out + ((size_t)(ba*Hn + h)*Ln + q) * JTOT;
            float p[15];
#pragma unroll
            for (int i = 0; i < 15; i++) p[i] = row[i*32 + lane];
            float m = p[0];
#pragma unroll
            for (int i = 1; i < 15; i++) m = fmaxf(m, p[i]);
#pragma unroll
            for (int off = 16; off; off >>= 1) m = fmaxf(m, __shfl_xor_sync(0xffffffffu, m, off));
            if (m == NEGINF) {
#pragma unroll
                for (int i = 0; i < 15; i++) { row[i*32 + lane] = 0.f; arow[i*32 + lane] = 0.f; }
            } else {
                float s = 0.f;
#pragma unroll
                for (int i = 0; i < 15; i++) { p[i] = __expf(p[i] - m); s += p[i]; }
#pragma unroll
                for (int off = 16; off; off >>= 1) s += __shfl_xor_sync(0xffffffffu, s, off);
                float inv = 1.f / s;
#pragma unroll
                for (int i = 0; i < 15; i++) {
                    float v = p[i] * inv;
                    row[i*32 + lane] = v;
                    arow[i*32 + lane] = v;
                }
            }
        }
    }
    __syncthreads();

    // P @ V : warp w owns kk = 2w, 2w+1; lane = q row (30 active).
    // V read from global: all active lanes read the SAME line -> broadcast LDG.
    const int w    = tid >> 5;
    const int lane = tid & 31;
    u64 acc[8];
#pragma unroll
    for (int d = 0; d < 8; d++) acc[d] = 0ULL;
    if (lane < Ln) {
        const float* prow = sc + lane*SCP;
#pragma unroll
        for (int half = 0; half < 2; half++) {
            const int kk = 2*w + half;
            const float4* vbase = reinterpret_cast<const float4*>(gv + rowbase[kk] + h*HDn);
            const int jbase = kk*Ln;
#pragma unroll 3
            for (int l = 0; l < Ln; l++) {
                float p = prow[jbase + l];
                u64 pp = pack2(p, p);
                const float4* src = vbase + l*(Mn/4);
                F4U2 v0, v1, v2, v3;
                v0.f = src[0]; v1.f = src[1]; v2.f = src[2]; v3.f = src[3];
                acc[0] = fma2(pp, v0.u[0], acc[0]); acc[1] = fma2(pp, v0.u[1], acc[1]);
                acc[2] = fma2(pp, v1.u[0], acc[2]); acc[3] = fma2(pp, v1.u[1], acc[3]);
                acc[4] = fma2(pp, v2.u[0], acc[4]); acc[5] = fma2(pp, v2.u[1], acc[5]);
                acc[6] = fma2(pp, v3.u[0], acc[6]); acc[7] = fma2(pp, v3.u[1], acc[7]);
            }
        }
    }
    __syncthreads();   // sc reads done; region reusable for partials
    if (lane < Ln) {
        float av[16];
#pragma unroll
        for (int d = 0; d < 8; d++) unpack2(acc[d], av[2*d], av[2*d+1]);
        float4* dst = reinterpret_cast<float4*>(sc + w*480 + lane*HDn);
#pragma unroll
        for (int c = 0; c < 4; c++)
            dst[c] = make_float4(av[c*4+0], av[c*4+1], av[c*4+2], av[c*4+3]);
    }
    __syncthreads();

    // reduce 8 partials and write ctx slice
    for (int e = tid; e < Ln*HDn; e += 256) {
        float s = 0.f;
#pragma unroll
        for (int ww = 0; ww < 8; ww++) s += sc[ww*480 + e];
        int q = e >> 4, d = e & 15;
        ctx_out[((size_t)ba*Ln + q)*Mn + h*HDn + d] = s;
    }
}

// ---------------------------------------------------------------------------
extern "C" void kernel_launch(void* const* d_in, const int* in_sizes, int n_in,
                              void* d_out, int out_size)
{
    const float* ff   = (const float*)d_in[0];
    const float* gb   = (const float*)d_in[1];
    const float* Wq   = (const float*)d_in[2];
    const float* bq   = (const float*)d_in[3];
    const float* Wk   = (const float*)d_in[4];
    const float* bk   = (const float*)d_in[5];
    const float* Wv   = (const float*)d_in[6];
    const float* bv   = (const float*)d_in[7];
    const float* Wo   = (const float*)d_in[8];
    const float* bo   = (const float*)d_in[9];
    const int*   nidx = (const int*)d_in[10];
    const void*  nmask = (const void*)d_in[11];

    float* out  = (float*)d_out;
    float* attn = out + (size_t)Bn*An*Ln*Mn;

    float *pq, *pk, *pv, *pctx;
    cudaGetSymbolAddress((void**)&pq,  g_q);
    cudaGetSymbolAddress((void**)&pk,  g_k);
    cudaGetSymbolAddress((void**)&pv,  g_v);
    cudaGetSymbolAddress((void**)&pctx, g_ctx);

    const int gemm_smem = (64*129 + 128*128) * 4;          // 98560 B
    const int attn_smem = (Ln*HDn + Ln*SCP) * 4;           // 59640 B
    cudaFuncSetAttribute(gemm_qkv_kernel, cudaFuncAttributeMaxDynamicSharedMemorySize, gemm_smem);
    cudaFuncSetAttribute(gemm64_kernel,   cudaFuncAttributeMaxDynamicSharedMemorySize, gemm_smem);
    cudaFuncSetAttribute(attn_kernel,     cudaFuncAttributeMaxDynamicSharedMemorySize, attn_smem);

    // 1: mask dtype detection
    detect_mask_kernel<<<1, 256>>>((const unsigned int*)nmask);

    // 2: fused QKV projections
    dim3 gqkv(NROWS/64, 3);
    gemm_qkv_kernel<<<gqkv, 256, gemm_smem>>>(ff, Wq, bq, pq, Wk, bk, pk, Wv, bv, pv);

    // 3: attention, single launch (4096 CTAs)
    attn_kernel<<<Bn*An*Hn, 256, attn_smem>>>(pq, pk, pv, gb, nidx, nmask, attn, pctx);

    // 4: output projection
    gemm64_kernel<<<NROWS/64, 256, gemm_smem>>>(pctx, Wo, bo, out);
}

// round 10
// speedup vs baseline: 1.1427x; 1.0180x over previous
#include <cuda_runtime.h>
#include <cuda_bf16.h>
#include <math_constants.h>

// Problem dims
#define Bn   8
#define An   64
#define Ln   30
#define Dn   128
#define Kn   16
#define Mn   128
#define Hn   8
#define HDn  16
#define NROWS (Bn*An*Ln)           // 15360
#define JTOT (Kn*Ln)               // 480
#define SCP  481                   // padded score stride
#define SCALE 0.25f
#define HSTRIDE 480                // floats per (ba,h) block in head-major layout
#define BASTRIDE 3840              // floats per ba block (8 heads)

// ---- packed f32x2 helpers (Blackwell FFMA2 path) ---------------------------
typedef unsigned long long u64;
union F4U2 { float4 f; u64 u[2]; };

__device__ __forceinline__ u64 pack2(float lo, float hi) {
    u64 r; asm("mov.b64 %0, {%1,%2};" : "=l"(r) : "f"(lo), "f"(hi)); return r;
}
__device__ __forceinline__ void unpack2(u64 v, float& lo, float& hi) {
    asm("mov.b64 {%0,%1}, %2;" : "=f"(lo), "=f"(hi) : "l"(v));
}
__device__ __forceinline__ u64 fma2(u64 a, u64 b, u64 c) {
    u64 d; asm("fma.rn.f32x2 %0, %1, %2, %3;" : "=l"(d) : "l"(a), "l"(b), "l"(c)); return d;
}

// Scratch (device globals; no allocation allowed)
// Q/K/V/ctx stored HEAD-MAJOR: [ba(512)][h(8)][l(30)][hd(16)]
__device__ float g_q[NROWS*Mn];
__device__ float g_k[NROWS*Mn];
__device__ float g_v[NROWS*Mn];
__device__ float g_ctx[NROWS*Mn];
__device__ int   g_mask_mode;      // 0 = u8/bool, 1 = int32, 2 = float32

// ---------------------------------------------------------------------------
__global__ void __launch_bounds__(256) detect_mask_kernel(const unsigned int* __restrict__ m)
{
    __shared__ int s_f32, s_hi;
    if (threadIdx.x == 0) { s_f32 = 0; s_hi = 0; }
    __syncthreads();
    int f32 = 0, hi = 0;
#pragma unroll
    for (int i = 0; i < 8; i++) {
        unsigned int w = m[threadIdx.x + 256*i];
        f32 |= (w == 0x3f800000u);
        hi  |= ((w & 0xFFFFFF00u) != 0u);
    }
    if (f32) s_f32 = 1;
    if (hi)  s_hi  = 1;
    __syncthreads();
    if (threadIdx.x == 0)
        g_mask_mode = s_f32 ? 2 : (s_hi ? 0 : 1);
}

// ---------------------------------------------------------------------------
// GEMM core: 64x128 CTA tile; X staged in smem (33KB); W via coalesced LDG
// (L1/L2 resident). Thread owns 4 rows x 8 consecutive cols (16 u64 acc).
// compute-only body; the caller does the epilogue (layout differs).
// ---------------------------------------------------------------------------
__device__ __forceinline__ void gemm_compute(
    const float* __restrict__ W, float* Xs, int tid, u64 acc[4][4])
{
    const int tx = tid & 15;
    const int ty = tid >> 4;
#pragma unroll
    for (int i = 0; i < 4; i++)
#pragma unroll
        for (int j = 0; j < 4; j++) acc[i][j] = 0ULL;

    const float4* Wg = reinterpret_cast<const float4*>(W);
#pragma unroll 8
    for (int k = 0; k < 128; k++) {
        u64 aa[4];
#pragma unroll
        for (int i = 0; i < 4; i++) {
            float a = Xs[(ty + 16*i)*129 + k];
            aa[i] = pack2(a, a);
        }
        F4U2 b0, b1;
        b0.f = __ldg(&Wg[k*32 + tx*2 + 0]);
        b1.f = __ldg(&Wg[k*32 + tx*2 + 1]);
        u64 bb[4] = {b0.u[0], b0.u[1], b1.u[0], b1.u[1]};
#pragma unroll
        for (int i = 0; i < 4; i++)
#pragma unroll
            for (int j = 0; j < 4; j++) acc[i][j] = fma2(aa[i], bb[j], acc[i][j]);
    }
}

// QKV GEMM: X = future_feat (row-major [15360,128]); writes HEAD-MAJOR.
__global__ void __launch_bounds__(256, 3) gemm_qkv_kernel(
    const float* __restrict__ X,
    const float* __restrict__ Wq, const float* __restrict__ bq, float* __restrict__ Cq,
    const float* __restrict__ Wk, const float* __restrict__ bk, float* __restrict__ Ck,
    const float* __restrict__ Wv, const float* __restrict__ bv, float* __restrict__ Cv)
{
    const float* W; const float* bias; float* C;
    if (blockIdx.y == 0)      { W = Wq; bias = bq; C = Cq; }
    else if (blockIdx.y == 1) { W = Wk; bias = bk; C = Ck; }
    else                      { W = Wv; bias = bv; C = Cv; }

    extern __shared__ float sm[];
    float* Xs = sm;                 // 64 x 129
    const int tid  = threadIdx.x;
    const int row0 = blockIdx.x * 64;

    const float4* Xg = reinterpret_cast<const float4*>(X + (size_t)row0 * 128);
#pragma unroll
    for (int i = 0; i < 8; i++) {
        int idx = tid + 256*i;
        float4 v = Xg[idx];
        int r = idx >> 5;
        int c = (idx & 31) * 4;
        Xs[r*129 + c + 0] = v.x;
        Xs[r*129 + c + 1] = v.y;
        Xs[r*129 + c + 2] = v.z;
        Xs[r*129 + c + 3] = v.w;
    }
    __syncthreads();

    u64 acc[4][4];
    gemm_compute(W, Xs, tid, acc);

    const int tx = tid & 15;
    const int ty = tid >> 4;
    const float4* bias4 = reinterpret_cast<const float4*>(bias);
    float4 bb0 = bias4[tx*2 + 0];
    float4 bb1 = bias4[tx*2 + 1];
    float bb[8] = {bb0.x, bb0.y, bb0.z, bb0.w, bb1.x, bb1.y, bb1.z, bb1.w};
    const int h   = tx >> 1;            // cols tx*8.. : head = tx/2
    const int hd0 = (tx & 1) * 8;
#pragma unroll
    for (int i = 0; i < 4; i++) {
        int r  = row0 + ty + 16*i;      // global row = ba*30 + l
        int ba = r / Ln;
        int l  = r - ba*Ln;
        float av[8];
#pragma unroll
        for (int j = 0; j < 4; j++) unpack2(acc[i][j], av[j*2], av[j*2+1]);
        float4* dst = reinterpret_cast<float4*>(C + (size_t)ba*BASTRIDE + h*HSTRIDE + l*HDn + hd0);
        dst[0] = make_float4(av[0]+bb[0], av[1]+bb[1], av[2]+bb[2], av[3]+bb[3]);
        dst[1] = make_float4(av[4]+bb[4], av[5]+bb[5], av[6]+bb[6], av[7]+bb[7]);
    }
}

// Output GEMM: X = ctx in HEAD-MAJOR; gathers into smem; writes row-major out.
__global__ void __launch_bounds__(256, 3) gemm_out_kernel(
    const float* __restrict__ Xhm, const float* __restrict__ W,
    const float* __restrict__ bias, float* __restrict__ C)
{
    extern __shared__ float sm[];
    float* Xs = sm;                 // 64 x 129
    const int tid  = threadIdx.x;
    const int row0 = blockIdx.x * 64;

#pragma unroll
    for (int i = 0; i < 8; i++) {
        int idx = tid + 256*i;          // float4 index in the 64x128 tile
        int r  = idx >> 5;              // tile row
        int c4 = idx & 31;              // float4 col
        int g  = row0 + r;              // global row = ba*30 + l
        int ba = g / Ln;
        int l  = g - ba*Ln;
        int h  = c4 >> 2;
        int hd = (c4 & 3) * 4;
        float4 v = *reinterpret_cast<const float4*>(
            Xhm + (size_t)ba*BASTRIDE + h*HSTRIDE + l*HDn + hd);
        int c = c4 * 4;
        Xs[r*129 + c + 0] = v.x;
        Xs[r*129 + c + 1] = v.y;
        Xs[r*129 + c + 2] = v.z;
        Xs[r*129 + c + 3] = v.w;
    }
    __syncthreads();

    u64 acc[4][4];
    gemm_compute(W, Xs, tid, acc);

    const int tx = tid & 15;
    const int ty = tid >> 4;
    const float4* bias4 = reinterpret_cast<const float4*>(bias);
    float4 bb0 = bias4[tx*2 + 0];
    float4 bb1 = bias4[tx*2 + 1];
    float bb[8] = {bb0.x, bb0.y, bb0.z, bb0.w, bb1.x, bb1.y, bb1.z, bb1.w};
#pragma unroll
    for (int i = 0; i < 4; i++) {
        int r = row0 + ty + 16*i;
        float av[8];
#pragma unroll
        for (int j = 0; j < 4; j++) unpack2(acc[i][j], av[j*2], av[j*2+1]);
        float4* dst = reinterpret_cast<float4*>(C + (size_t)r*128 + tx*8);
        dst[0] = make_float4(av[0]+bb[0], av[1]+bb[1], av[2]+bb[2], av[3]+bb[3]);
        dst[1] = make_float4(av[4]+bb[4], av[5]+bb[5], av[6]+bb[6], av[7]+bb[7]);
    }
}

// ---------------------------------------------------------------------------
// Attention: one 256-thread CTA per (b, a, h); 3 CTAs/SM.
// HEAD-MAJOR Q/K/V: all per-CTA slices are contiguous 1920B blocks.
// K loaded straight global->regs (coalesced). V broadcast-LDG in P@V.
// smem: qs[480] | sc[30*481] = 59640 B
// ---------------------------------------------------------------------------
__global__ void __launch_bounds__(256, 3) attn_kernel(
    const float* __restrict__ gq, const float* __restrict__ gk,
    const float* __restrict__ gv, const float* __restrict__ geom_bias,
    const int* __restrict__ nidx, const void* __restrict__ nmask,
    float* __restrict__ attn_out, float* __restrict__ ctx_out)
{
    const int bid = blockIdx.x;
    const int h  = bid & 7;
    const int a  = (bid >> 3) & 63;
    const int b  = bid >> 9;
    const int ba = b*An + a;
    const int tid = threadIdx.x;

    extern __shared__ float sm[];
    float* qs = sm;                    // 480 floats
    float* sc = qs + Ln*HDn;           // 30*481 (scores -> partials)

    __shared__ int   rowbase[Kn];      // head-major base (floats) per neighbour
    __shared__ float biasS[Kn];
    __shared__ int   maskS[Kn];

    if (tid < Kn) {
        int n = nidx[ba*Kn + tid];
        rowbase[tid] = ((b*An + n)*Hn + h) * HSTRIDE;
        biasS[tid]   = geom_bias[ba*Kn + tid];
        int mode = g_mask_mode;
        bool mv;
        if (mode == 0)      mv = ((const unsigned char*)nmask)[ba*Kn + tid] != 0;
        else if (mode == 1) mv = ((const int*)nmask)[ba*Kn + tid] != 0;
        else                mv = ((const float*)nmask)[ba*Kn + tid] != 0.0f;
        maskS[tid] = mv ? 1 : 0;
    }
    // q head slice: contiguous 480 floats = 120 float4
    if (tid < Ln*4) {
        const float4* qbase = reinterpret_cast<const float4*>(gq + (size_t)(ba*Hn + h)*HSTRIDE);
        reinterpret_cast<float4*>(qs)[tid] = qbase[tid];
    }
    __syncthreads();   // rowbase + qs ready

    // K rows straight from global into PACKED registers (coalesced: contiguous
    // 64B rows within each neighbour's 1920B block).
    const int j0 = tid;
    const int j1 = tid + 256;
    const bool hasJ1 = (tid < JTOT - 256);   // tid < 224
    const int kk0 = j0 / Ln;
    const int l0  = j0 - kk0*Ln;
    const int kk1 = j1 / Ln;
    const int l1  = j1 - kk1*Ln;
    u64 k0[8], k1[8];
    {
        const float4* src0 = reinterpret_cast<const float4*>(gk + rowbase[kk0] + l0*HDn);
        F4U2 t;
#pragma unroll
        for (int c = 0; c < 4; c++) {
            t.f = src0[c];
            k0[c*2+0] = t.u[0]; k0[c*2+1] = t.u[1];
        }
        if (hasJ1) {
            const float4* src1 = reinterpret_cast<const float4*>(gk + rowbase[kk1] + l1*HDn);
#pragma unroll
            for (int c = 0; c < 4; c++) {
                t.f = src1[c];
                k1[c*2+0] = t.u[0]; k1[c*2+1] = t.u[1];
            }
        }
    }
    const float bias0 = biasS[kk0];
    const bool  m0 = maskS[kk0] != 0;
    const float bias1 = hasJ1 ? biasS[kk1] : 0.f;
    const bool  m1 = hasJ1 ? (maskS[kk1] != 0) : false;

    // scores from packed register K
    const float NEGINF = -CUDART_INF_F;
    const float4* qs4 = reinterpret_cast<const float4*>(qs);
#pragma unroll 1
    for (int qp = 0; qp < Ln/2; qp++) {
        int q0 = qp * 2;
        u64 qa[8], qb[8];
        {
            F4U2 t;
#pragma unroll
            for (int c = 0; c < 4; c++) {
                t.f = qs4[q0*4 + c];
                qa[c*2+0] = t.u[0]; qa[c*2+1] = t.u[1];
            }
#pragma unroll
            for (int c = 0; c < 4; c++) {
                t.f = qs4[(q0+1)*4 + c];
                qb[c*2+0] = t.u[0]; qb[c*2+1] = t.u[1];
            }
        }
        u64 p00 = 0ULL, p10 = 0ULL, p01 = 0ULL, p11 = 0ULL;
#pragma unroll
        for (int d = 0; d < 8; d++) {
            p00 = fma2(qa[d], k0[d], p00);
            p10 = fma2(qb[d], k0[d], p10);
        }
        if (hasJ1) {
#pragma unroll
            for (int d = 0; d < 8; d++) {
                p01 = fma2(qa[d], k1[d], p01);
                p11 = fma2(qb[d], k1[d], p11);
            }
        }
        float lo, hi;
        unpack2(p00, lo, hi); float s00 = lo + hi;
        unpack2(p10, lo, hi); float s10 = lo + hi;
        sc[q0*SCP + j0]     = m0 ? fmaf(s00, SCALE, bias0) : NEGINF;
        sc[(q0+1)*SCP + j0] = m0 ? fmaf(s10, SCALE, bias0) : NEGINF;
        if (hasJ1) {
            unpack2(p01, lo, hi); float s01 = lo + hi;
            unpack2(p11, lo, hi); float s11 = lo + hi;
            sc[q0*SCP + j1]     = m1 ? fmaf(s01, SCALE, bias1) : NEGINF;
            sc[(q0+1)*SCP + j1] = m1 ? fmaf(s11, SCALE, bias1) : NEGINF;
        }
    }
    __syncthreads();

    // softmax: one warp per row, 15 elements per lane held in registers
    {
        const int warp = tid >> 5, lane = tid & 31;
        for (int q = warp; q < Ln; q += 8) {
            float* row = sc + q*SCP;
            float* arow = attn_out + ((size_t)(ba*Hn + h)*Ln + q) * JTOT;
            float p[15];
#pragma unroll
            for (int i = 0; i < 15; i++) p[i] = row[i*32 + lane];
            float m = p[0];
#pragma unroll
            for (int i = 1; i < 15; i++) m = fmaxf(m, p[i]);
#pragma unroll
            for (int off = 16; off; off >>= 1) m = fmaxf(m, __shfl_xor_sync(0xffffffffu, m, off));
            if (m == NEGINF) {
#pragma unroll
                for (int i = 0; i < 15; i++) { row[i*32 + lane] = 0.f; arow[i*32 + lane] = 0.f; }
            } else {
                float s = 0.f;
#pragma unroll
                for (int i = 0; i < 15; i++) { p[i] = __expf(p[i] - m); s += p[i]; }
#pragma unroll
                for (int off = 16; off; off >>= 1) s += __shfl_xor_sync(0xffffffffu, s, off);
                float inv = 1.f / s;
#pragma unroll
                for (int i = 0; i < 15; i++) {
                    float v = p[i] * inv;
                    row[i*32 + lane] = v;
                    arow[i*32 + lane] = v;
                }
            }
        }
    }
    __syncthreads();

    // P @ V : warp w owns kk = 2w, 2w+1; lane = q row (30 active).
    // V broadcast-LDG from contiguous head-major rows.
    const int w    = tid >> 5;
    const int lane = tid & 31;
    u64 acc[8];
#pragma unroll
    for (int d = 0; d < 8; d++) acc[d] = 0ULL;
    if (lane < Ln) {
        const float* prow = sc + lane*SCP;
#pragma unroll
        for (int half = 0; half < 2; half++) {
            const int kk = 2*w + half;
            const float4* vbase = reinterpret_cast<const float4*>(gv + rowbase[kk]);
            const int jbase = kk*Ln;
#pragma unroll 3
            for (int l = 0; l < Ln; l++) {
                float p = prow[jbase + l];
                u64 pp = pack2(p, p);
                const float4* src = vbase + l*4;
                F4U2 v0, v1, v2, v3;
                v0.f = src[0]; v1.f = src[1]; v2.f = src[2]; v3.f = src[3];
                acc[0] = fma2(pp, v0.u[0], acc[0]); acc[1] = fma2(pp, v0.u[1], acc[1]);
                acc[2] = fma2(pp, v1.u[0], acc[2]); acc[3] = fma2(pp, v1.u[1], acc[3]);
                acc[4] = fma2(pp, v2.u[0], acc[4]); acc[5] = fma2(pp, v2.u[1], acc[5]);
                acc[6] = fma2(pp, v3.u[0], acc[6]); acc[7] = fma2(pp, v3.u[1], acc[7]);
            }
        }
    }
    __syncthreads();   // sc reads done; region reusable for partials
    if (lane < Ln) {
        float av[16];
#pragma unroll
        for (int d = 0; d < 8; d++) unpack2(acc[d], av[2*d], av[2*d+1]);
        float4* dst = reinterpret_cast<float4*>(sc + w*480 + lane*HDn);
#pragma unroll
        for (int c = 0; c < 4; c++)
            dst[c] = make_float4(av[c*4+0], av[c*4+1], av[c*4+2], av[c*4+3]);
    }
    __syncthreads();

    // reduce 8 partials, write ctx HEAD-MAJOR (contiguous 480 floats per CTA)
    float* ctxbase = ctx_out + (size_t)(ba*Hn + h)*HSTRIDE;
    for (int e = tid; e < Ln*HDn; e += 256) {
        float s = 0.f;
#pragma unroll
        for (int ww = 0; ww < 8; ww++) s += sc[ww*480 + e];
        ctxbase[e] = s;
    }
}

// ---------------------------------------------------------------------------
extern "C" void kernel_launch(void* const* d_in, const int* in_sizes, int n_in,
                              void* d_out, int out_size)
{
    const float* ff   = (const float*)d_in[0];
    const float* gb   = (const float*)d_in[1];
    const float* Wq   = (const float*)d_in[2];
    const float* bq   = (const float*)d_in[3];
    const float* Wk   = (const float*)d_in[4];
    const float* bk   = (const float*)d_in[5];
    const float* Wv   = (const float*)d_in[6];
    const float* bv   = (const float*)d_in[7];
    const float* Wo   = (const float*)d_in[8];
    const float* bo   = (const float*)d_in[9];
    const int*   nidx = (const int*)d_in[10];
    const void*  nmask = (const void*)d_in[11];

    float* out  = (float*)d_out;
    float* attn = out + (size_t)Bn*An*Ln*Mn;

    float *pq, *pk, *pv, *pctx;
    cudaGetSymbolAddress((void**)&pq,  g_q);
    cudaGetSymbolAddress((void**)&pk,  g_k);
    cudaGetSymbolAddress((void**)&pv,  g_v);
    cudaGetSymbolAddress((void**)&pctx, g_ctx);

    const int gemm_smem = 64*129*4;                        // 33024 B
    const int attn_smem = (Ln*HDn + Ln*SCP) * 4;           // 59640 B
    cudaFuncSetAttribute(gemm_qkv_kernel, cudaFuncAttributeMaxDynamicSharedMemorySize, gemm_smem);
    cudaFuncSetAttribute(gemm_out_kernel, cudaFuncAttributeMaxDynamicSharedMemorySize, gemm_smem);
    cudaFuncSetAttribute(attn_kernel,     cudaFuncAttributeMaxDynamicSharedMemorySize, attn_smem);

    // 1: mask dtype detection
    detect_mask_kernel<<<1, 256>>>((const unsigned int*)nmask);

    // 2: fused QKV projections (head-major outputs)
    dim3 gqkv(NROWS/64, 3);
    gemm_qkv_kernel<<<gqkv, 256, gemm_smem>>>(ff, Wq, bq, pq, Wk, bk, pk, Wv, bv, pv);

    // 3: attention, single launch (4096 CTAs)
    attn_kernel<<<Bn*An*Hn, 256, attn_smem>>>(pq, pk, pv, gb, nidx, nmask, attn, pctx);

    // 4: output projection (head-major ctx -> row-major out)
    gemm_out_kernel<<<NROWS/64, 256, gemm_smem>>>(pctx, Wo, bo, out);
}